// round 7
// baseline (speedup 1.0000x reference)
#include <cuda_runtime.h>

// x: (16, 256, 128, 128) fp32 -> 2x2 block sum * 0.5, then 2x2 NN upsample.
//
// R7: persistent grid-stride kernel. One wave (148 SMs x 8 CTAs x 256 thr =
// 303,104 threads), each thread loops over ~14 work items. Keeps every warp's
// load stream continuous across items (no per-CTA pipeline drain, no wave
// transitions). Access form = R6's best: LDG.256/STG.256 + .cs streaming.
//
// Work item = one v8 slot (8 consecutive floats) x one row pair.
// Row = 128 floats = 16 v8 slots; 16*256*64 row pairs -> 4,194,304 items.

#define NITEMS (16 * 256 * 64 * 16)   // 4,194,304

__global__ void __launch_bounds__(256) wfdm_kernel(
    const float* __restrict__ in, float* __restrict__ out, int stride)
{
    int tid = blockIdx.x * blockDim.x + threadIdx.x;

    for (int i = tid; i < NITEMS; i += stride) {
        int col   = i & 15;        // v8 slot within row, lane-contiguous
        int group = i >> 4;        // row pair index

        long base = (long)group * 256 + (long)col * 8;

        const float* p0 = in + base;       // top row
        const float* p1 = p0 + 128;        // bottom row

        float a0, a1, a2, a3, a4, a5, a6, a7;
        float b0, b1, b2, b3, b4, b5, b6, b7;

        asm volatile(
            "ld.global.cs.v8.f32 {%0,%1,%2,%3,%4,%5,%6,%7}, [%8];"
            : "=f"(a0), "=f"(a1), "=f"(a2), "=f"(a3),
              "=f"(a4), "=f"(a5), "=f"(a6), "=f"(a7)
            : "l"(p0));
        asm volatile(
            "ld.global.cs.v8.f32 {%0,%1,%2,%3,%4,%5,%6,%7}, [%8];"
            : "=f"(b0), "=f"(b1), "=f"(b2), "=f"(b3),
              "=f"(b4), "=f"(b5), "=f"(b6), "=f"(b7)
            : "l"(p1));

        float s0 = (a0 + a1 + b0 + b1) * 0.5f;
        float s1 = (a2 + a3 + b2 + b3) * 0.5f;
        float s2 = (a4 + a5 + b4 + b5) * 0.5f;
        float s3 = (a6 + a7 + b6 + b7) * 0.5f;

        float* q0 = out + base;
        float* q1 = q0 + 128;

        asm volatile(
            "st.global.cs.v8.f32 [%0], {%1,%2,%3,%4,%5,%6,%7,%8};"
            :: "l"(q0),
               "f"(s0), "f"(s0), "f"(s1), "f"(s1),
               "f"(s2), "f"(s2), "f"(s3), "f"(s3)
            : "memory");
        asm volatile(
            "st.global.cs.v8.f32 [%0], {%1,%2,%3,%4,%5,%6,%7,%8};"
            :: "l"(q1),
               "f"(s0), "f"(s0), "f"(s1), "f"(s1),
               "f"(s2), "f"(s2), "f"(s3), "f"(s3)
            : "memory");
    }
}

extern "C" void kernel_launch(void* const* d_in, const int* in_sizes, int n_in,
                              void* d_out, int out_size)
{
    const float* in = (const float*)d_in[0];
    float* out = (float*)d_out;

    // One wave: 148 SMs (GB300: 152, use 148 to be safe for full residency)
    // x 8 CTAs/SM (24 regs, 256 thr -> 8 CTAs = 64 warps/SM fits).
    int threads = 256;
    int blocks = 148 * 8;          // 1184 CTAs, single wave
    int stride = blocks * threads; // 303,104
    wfdm_kernel<<<blocks, threads>>>(in, out, stride);
}

// round 8
// speedup vs baseline: 1.1115x; 1.1115x over previous
#include <cuda_runtime.h>

// x: (16, 256, 128, 128) fp32 -> 2x2 block sum * 0.5, then 2x2 NN upsample.
//
// R8: flat grid (HW distributor pipelines CTAs; R7 showed persistent loops
// serialize around the store fence). Straight-line body, 32 floats in / 32
// out per thread: 4 x LDG.256 front-batched (MLP=4 @ 32B) + 4 x STG.256,
// all .cs evict-first. Lane-contiguous v8 slots -> perfect coalescing.
//
// Work item = one v8 slot x TWO row pairs (4 consecutive rows).
// Row = 128 floats = 16 v8 slots; group g covers rows [4g, 4g+3].
// 16*256*32 groups x 16 slots = 2,097,152 threads = 8192 CTAs @ 256.

__global__ void __launch_bounds__(256) wfdm_kernel(
    const float* __restrict__ in, float* __restrict__ out)
{
    int tid = blockIdx.x * blockDim.x + threadIdx.x;

    int col   = tid & 15;      // v8 slot within row (0..15), lane-contiguous
    int group = tid >> 4;      // group of 4 rows (2 row pairs)

    long base = (long)group * 512 + (long)col * 8;   // 4 rows * 128 floats

    const float* p0 = in + base;         // row 4g
    const float* p1 = p0 + 128;          // row 4g+1
    const float* p2 = p0 + 256;          // row 4g+2
    const float* p3 = p0 + 384;          // row 4g+3

    float a0,a1,a2,a3,a4,a5,a6,a7;       // row 4g
    float b0,b1,b2,b3,b4,b5,b6,b7;       // row 4g+1
    float c0,c1,c2,c3,c4,c5,c6,c7;       // row 4g+2
    float d0,d1,d2,d3,d4,d5,d6,d7;       // row 4g+3

    asm volatile("ld.global.cs.v8.f32 {%0,%1,%2,%3,%4,%5,%6,%7}, [%8];"
        : "=f"(a0),"=f"(a1),"=f"(a2),"=f"(a3),"=f"(a4),"=f"(a5),"=f"(a6),"=f"(a7)
        : "l"(p0));
    asm volatile("ld.global.cs.v8.f32 {%0,%1,%2,%3,%4,%5,%6,%7}, [%8];"
        : "=f"(b0),"=f"(b1),"=f"(b2),"=f"(b3),"=f"(b4),"=f"(b5),"=f"(b6),"=f"(b7)
        : "l"(p1));
    asm volatile("ld.global.cs.v8.f32 {%0,%1,%2,%3,%4,%5,%6,%7}, [%8];"
        : "=f"(c0),"=f"(c1),"=f"(c2),"=f"(c3),"=f"(c4),"=f"(c5),"=f"(c6),"=f"(c7)
        : "l"(p2));
    asm volatile("ld.global.cs.v8.f32 {%0,%1,%2,%3,%4,%5,%6,%7}, [%8];"
        : "=f"(d0),"=f"(d1),"=f"(d2),"=f"(d3),"=f"(d4),"=f"(d5),"=f"(d6),"=f"(d7)
        : "l"(p3));

    // Row pair 0 (rows 4g, 4g+1)
    float s0 = (a0 + a1 + b0 + b1) * 0.5f;
    float s1 = (a2 + a3 + b2 + b3) * 0.5f;
    float s2 = (a4 + a5 + b4 + b5) * 0.5f;
    float s3 = (a6 + a7 + b6 + b7) * 0.5f;
    // Row pair 1 (rows 4g+2, 4g+3)
    float t0 = (c0 + c1 + d0 + d1) * 0.5f;
    float t1 = (c2 + c3 + d2 + d3) * 0.5f;
    float t2 = (c4 + c5 + d4 + d5) * 0.5f;
    float t3 = (c6 + c7 + d6 + d7) * 0.5f;

    float* q0 = out + base;
    float* q1 = q0 + 128;
    float* q2 = q0 + 256;
    float* q3 = q0 + 384;

    asm volatile("st.global.cs.v8.f32 [%0], {%1,%2,%3,%4,%5,%6,%7,%8};"
        :: "l"(q0), "f"(s0),"f"(s0),"f"(s1),"f"(s1),"f"(s2),"f"(s2),"f"(s3),"f"(s3)
        : "memory");
    asm volatile("st.global.cs.v8.f32 [%0], {%1,%2,%3,%4,%5,%6,%7,%8};"
        :: "l"(q1), "f"(s0),"f"(s0),"f"(s1),"f"(s1),"f"(s2),"f"(s2),"f"(s3),"f"(s3)
        : "memory");
    asm volatile("st.global.cs.v8.f32 [%0], {%1,%2,%3,%4,%5,%6,%7,%8};"
        :: "l"(q2), "f"(t0),"f"(t0),"f"(t1),"f"(t1),"f"(t2),"f"(t2),"f"(t3),"f"(t3)
        : "memory");
    asm volatile("st.global.cs.v8.f32 [%0], {%1,%2,%3,%4,%5,%6,%7,%8};"
        :: "l"(q3), "f"(t0),"f"(t0),"f"(t1),"f"(t1),"f"(t2),"f"(t2),"f"(t3),"f"(t3)
        : "memory");
}

extern "C" void kernel_launch(void* const* d_in, const int* in_sizes, int n_in,
                              void* d_out, int out_size)
{
    const float* in = (const float*)d_in[0];
    float* out = (float*)d_out;

    // total threads = elements / 32 (each thread covers 32 floats)
    int total = out_size / 32;   // 16*256*128*128 / 32 = 2,097,152
    int threads = 256;
    int blocks = total / threads;  // exact: 8192
    wfdm_kernel<<<blocks, threads>>>(in, out);
}

// round 9
// speedup vs baseline: 1.1289x; 1.0157x over previous
#include <cuda_runtime.h>

// x: (16, 256, 128, 128) fp32 -> 2x2 block sum * 0.5, then 2x2 NN upsample.
//
// R9: best-measured form (R4: float4 lane-contiguous, 4 front-batched
// LDG.128 + 4 STG.128, .cs evict-first) with ONE variable changed:
// block size 256 -> 512. Fewer resident CTAs per SM (8 -> 4) cuts the
// cross-CTA L1tex queue depth (oe*MLP_p1: 32 -> 16 ~= Q_th), reducing
// late-CTA spread at wave boundaries.
//
// Each thread: one float4 column slot x two row pairs (4 consecutive rows).
// Row = 128 floats = 32 float4. 16*256*32 groups x 32 slots = 4,194,304
// threads = 8192 CTAs @ 512.

__global__ void __launch_bounds__(512) wfdm_kernel(
    const float4* __restrict__ in, float4* __restrict__ out)
{
    int tid = blockIdx.x * blockDim.x + threadIdx.x;

    int col   = tid & 31;      // float4 slot within row (0..31), lane-contiguous
    int group = tid >> 5;      // group of 4 rows (2 row pairs)

    int base = group * 128 + col;   // 4 rows * 32 float4/row

    // Front-batched independent loads, all lane-stride-1: MLP = 4
    float4 t0 = __ldcs(&in[base]);         // row 4g
    float4 b0 = __ldcs(&in[base + 32]);    // row 4g+1
    float4 t1 = __ldcs(&in[base + 64]);    // row 4g+2
    float4 b1 = __ldcs(&in[base + 96]);    // row 4g+3

    // Row pair 0
    float s0 = (t0.x + t0.y + b0.x + b0.y) * 0.5f;
    float s1 = (t0.z + t0.w + b0.z + b0.w) * 0.5f;
    // Row pair 1
    float s2 = (t1.x + t1.y + b1.x + b1.y) * 0.5f;
    float s3 = (t1.z + t1.w + b1.z + b1.w) * 0.5f;

    float4 o0 = make_float4(s0, s0, s1, s1);
    float4 o1 = make_float4(s2, s2, s3, s3);

    __stcs(&out[base],      o0);
    __stcs(&out[base + 32], o0);
    __stcs(&out[base + 64], o1);
    __stcs(&out[base + 96], o1);
}

extern "C" void kernel_launch(void* const* d_in, const int* in_sizes, int n_in,
                              void* d_out, int out_size)
{
    const float4* in = (const float4*)d_in[0];
    float4* out = (float4*)d_out;

    // total threads = elements / 16 (each thread covers 16 floats)
    int total = out_size / 16;   // 16*256*128*128 / 16 = 4,194,304
    int threads = 512;
    int blocks = total / threads;  // exact: 8192
    wfdm_kernel<<<blocks, threads>>>(in, out);
}